// round 15
// baseline (speedup 1.0000x reference)
#include <cuda_runtime.h>

// NeuralTMT — GB300 sm_103a, round 14: K1 4-stream gather (2 independent
// loads per lane per iteration, 12-13-deep chains, reg headroom for load
// batching). K2 unchanged (8-lane sub-warp tasks).
// Inputs (metadata order): IL[4,V,64] f32, LI[4,V,64] f32, UI[4,U,64] f32,
// IU[V,64] f32, alpha[4] f32, uid[B] i32, baskets[4,B,50] i32,
// iid[4,B] i32, neg_iid[4,B] i32. Output f32[8*B].

#define TMT_V 100001
#define TMT_U 100000
#define TMT_K 64
#define TMT_B 16384
#define TMT_L 50
#define TMT_NEG_BIG (-4294967295.0f)   // -(2^32)+1
#define K1_NB 8                         // batch elements per K1 CTA

// Scratch: x[b][period][k]  (16384 * 4 * 64 f32 = 16.8 MB)
__device__ float g_x[(long long)TMT_B * 4 * TMT_K];

__device__ __forceinline__ float dot4(float4 a, float4 b) {
    return a.x * b.x + a.y * b.y + a.z * b.z + a.w * b.w;
}

// ---------------------------------------------------------------------------
// K1: x[b,p,:] = (1/L) * sum_l LI[p, baskets[p,b,l], :]
// grid = (B/8, 4), blockIdx.y = period (period-major dispatch order).
// Warp owns one b. lane = s*8 + q: s in {0..3} = l-stream (13/13/12/12),
// q in {0..7} = float4 slot; each lane loads row-half slots q and q+8
// (2 independent 16 B loads per iteration). Streams combined via shfl.
// ---------------------------------------------------------------------------
__global__ __launch_bounds__(256, 6)
void tmt_gather_kernel(const float* __restrict__ LI,
                       const int*   __restrict__ baskets)
{
    __shared__ int sidx[K1_NB * TMT_L];          // 400 ints

    const int p  = blockIdx.y;
    const int b0 = blockIdx.x * K1_NB;
    const int t  = threadIdx.x;

    // Strided stage — 400 ints, 256 threads.
    const int* bb = baskets + ((long long)p * TMT_B + b0) * TMT_L;
    #pragma unroll
    for (int i = t; i < K1_NB * TMT_L; i += 256)
        sidx[i] = bb[i];
    __syncthreads();

    const int bl   = t >> 5;                     // 0..7 local batch element
    const int lane = t & 31;
    const int s    = lane >> 3;                  // l-stream 0..3
    const int q    = lane & 7;                   // float4 slot 0..7

    const float4* LIs = (const float4*)(LI + (long long)p * TMT_V * TMT_K);
    const int* idxp = sidx + bl * TMT_L;

    // Stream ranges: s0:[0,13) s1:[13,26) s2:[26,38) s3:[38,50)
    const int off = (s < 2) ? s * 13 : 26 + (s - 2) * 12;

    float4 a0 = make_float4(0.f, 0.f, 0.f, 0.f);
    float4 a1 = make_float4(0.f, 0.f, 0.f, 0.f);

    #pragma unroll
    for (int i = 0; i < 12; ++i) {
        const int idx = idxp[off + i];           // broadcast LDS
        const float4* r = LIs + (long long)idx * (TMT_K / 4);
        const float4 v0 = __ldg(r + q);
        const float4 v1 = __ldg(r + 8 + q);
        a0.x += v0.x; a0.y += v0.y; a0.z += v0.z; a0.w += v0.w;
        a1.x += v1.x; a1.y += v1.y; a1.z += v1.z; a1.w += v1.w;
    }
    if (s < 2) {                                  // 13th element for s0, s1
        const int idx = idxp[off + 12];
        const float4* r = LIs + (long long)idx * (TMT_K / 4);
        const float4 v0 = __ldg(r + q);
        const float4 v1 = __ldg(r + 8 + q);
        a0.x += v0.x; a0.y += v0.y; a0.z += v0.z; a0.w += v0.w;
        a1.x += v1.x; a1.y += v1.y; a1.z += v1.z; a1.w += v1.w;
    }

    // Combine the 4 streams (s = lane bits 3,4): xor 8 then xor 16.
    #pragma unroll
    for (int d = 8; d <= 16; d <<= 1) {
        a0.x += __shfl_xor_sync(0xffffffffu, a0.x, d);
        a0.y += __shfl_xor_sync(0xffffffffu, a0.y, d);
        a0.z += __shfl_xor_sync(0xffffffffu, a0.z, d);
        a0.w += __shfl_xor_sync(0xffffffffu, a0.w, d);
        a1.x += __shfl_xor_sync(0xffffffffu, a1.x, d);
        a1.y += __shfl_xor_sync(0xffffffffu, a1.y, d);
        a1.z += __shfl_xor_sync(0xffffffffu, a1.z, d);
        a1.w += __shfl_xor_sync(0xffffffffu, a1.w, d);
    }

    if (s == 0) {
        const float inv = 1.0f / (float)TMT_L;
        a0.x *= inv; a0.y *= inv; a0.z *= inv; a0.w *= inv;
        a1.x *= inv; a1.y *= inv; a1.z *= inv; a1.w *= inv;
        float4* xp =
            (float4*)(g_x + (((long long)(b0 + bl)) * 4 + p) * TMT_K);
        xp[q]     = a0;
        xp[q + 8] = a1;
    }
}

// ---------------------------------------------------------------------------
// K2: 8-lane sub-warp per (b_local, period, pos/neg) task.
// 256 threads = 8 warps = 32 groups = 32 tasks = 4 batch elements per CTA.
// ---------------------------------------------------------------------------
__global__ __launch_bounds__(256, 8)
void tmt_score_kernel(const float* __restrict__ IL,
                      const float* __restrict__ UI,
                      const float* __restrict__ IU,
                      const float* __restrict__ alpha,
                      const int*   __restrict__ uid,
                      const int*   __restrict__ iid,
                      const int*   __restrict__ neg_iid,
                      float*       __restrict__ out)
{
    __shared__ float xs[4][4][TMT_K];            // [b_local][period][k] = 4 KB

    const int t  = threadIdx.x;
    const int b0 = blockIdx.x * 4;

    // Stage x for this CTA's 4 batch elements (contiguous 4 KB in g_x).
    {
        const float4* src = (const float4*)(g_x + (long long)b0 * 4 * TMT_K);
        float4* dst = (float4*)&xs[0][0][0];
        #pragma unroll
        for (int i = t; i < 4 * 4 * TMT_K / 4; i += 256)
            dst[i] = src[i];
    }
    __syncthreads();

    const int w    = t >> 5;                     // warp 0..7
    const int lane = t & 31;
    const int g    = lane >> 3;                  // group 0..3 within warp
    const int kl   = lane & 7;                   // lane within group

    const int task = w * 4 + g;                  // 0..31
    const int bl   = task >> 3;                  // b_local
    const int p    = (task >> 1) & 3;            // period
    const int neg  = task & 1;
    const int gb   = b0 + bl;

    const int item = __ldg((neg ? neg_iid : iid) + p * TMT_B + gb);

    // Target row: two float4 per lane, coalesced 128 B per group request.
    const float4* tgt4 =
        (const float4*)(IL + ((long long)p * TMT_V + item) * TMT_K);
    const float4 ta = __ldg(tgt4 + kl);
    const float4 tc = __ldg(tgt4 + 8 + kl);

    // Partial dots over this lane's 8 k-elements.
    const float4* xs0 = (const float4*)xs[bl][0];
    const float4* xs1 = (const float4*)xs[bl][1];
    const float4* xs2 = (const float4*)xs[bl][2];
    const float4* xs3 = (const float4*)xs[bl][3];
    float d0 = dot4(xs0[kl], ta) + dot4(xs0[8 + kl], tc);
    float d1 = dot4(xs1[kl], ta) + dot4(xs1[8 + kl], tc);
    float d2 = dot4(xs2[kl], ta) + dot4(xs2[8 + kl], tc);
    float d3 = dot4(xs3[kl], ta) + dot4(xs3[8 + kl], tc);

    const float4* u4 =
        (const float4*)(UI + ((long long)p * TMT_U + __ldg(uid + gb)) * TMT_K);
    const float4* iu4 = (const float4*)(IU + (long long)item * TMT_K);
    float dm = dot4(__ldg(u4 + kl), __ldg(iu4 + kl))
             + dot4(__ldg(u4 + 8 + kl), __ldg(iu4 + 8 + kl));

    // 3-stage butterfly within each 8-lane group.
    #pragma unroll
    for (int off = 4; off > 0; off >>= 1) {
        d0 += __shfl_xor_sync(0xffffffffu, d0, off);
        d1 += __shfl_xor_sync(0xffffffffu, d1, off);
        d2 += __shfl_xor_sync(0xffffffffu, d2, off);
        d3 += __shfl_xor_sync(0xffffffffu, d3, off);
        dm += __shfl_xor_sync(0xffffffffu, dm, off);
    }

    if (kl == 0) {
        float d[4] = {d0, d1, d2, d3};
        float wv[4];
        float mx = -3.402823466e38f;
        #pragma unroll
        for (int i = 0; i < 4; ++i) {
            float v = d[i] * 0.125f;             // / sqrt(64)
            if (v == 0.0f) v = TMT_NEG_BIG;      // mask exact zeros
            wv[i] = v;
            mx = fmaxf(mx, v);
        }
        float sum = 0.0f;
        #pragma unroll
        for (int i = 0; i < 4; ++i) { wv[i] = expf(wv[i] - mx); sum += wv[i]; }
        float attn = 0.0f;
        #pragma unroll
        for (int i = 0; i < 4; ++i) attn += wv[i] * d[i];
        attn /= sum;

        const float a  = __ldg(alpha + p);
        const float sg = 1.0f / (1.0f + expf(-a));
        out[(2 * p + neg) * TMT_B + gb] = sg * attn + (1.0f - sg) * dm;
    }
}

extern "C" void kernel_launch(void* const* d_in, const int* in_sizes, int n_in,
                              void* d_out, int out_size)
{
    const float* IL      = (const float*)d_in[0];
    const float* LI      = (const float*)d_in[1];
    const float* UI      = (const float*)d_in[2];
    const float* IU      = (const float*)d_in[3];
    const float* alpha   = (const float*)d_in[4];
    const int*   uid     = (const int*)  d_in[5];
    const int*   baskets = (const int*)  d_in[6];
    const int*   iid     = (const int*)  d_in[7];
    const int*   neg_iid = (const int*)  d_in[8];
    float*       out     = (float*)d_out;

    dim3 g1(TMT_B / K1_NB, 4);
    tmt_gather_kernel<<<g1, 256>>>(LI, baskets);
    tmt_score_kernel<<<TMT_B / 4, 256>>>(IL, UI, IU, alpha, uid,
                                         iid, neg_iid, out);
}